// round 3
// baseline (speedup 1.0000x reference)
#include <cuda_runtime.h>
#include <stdint.h>

// Problem constants (fixed shapes)
#define GRID_N   8
#define L_SITES  64          // GRID*GRID
#define PW       3
#define S_SIZE   9           // PW*PW
#define N_PLAQ   64
#define LOCAL_D  2
#define M_DIM    128
#define BATCH    2048
#define N_PAT    512         // 2^9

// Scratch table: T[p][pattern] = sum_m prod_s eps[bit_s, p, m, s]
__device__ float g_table[N_PLAQ * N_PAT];   // 512 KB (L2-resident)

// ---------------------------------------------------------------------------
// Kernel 1: build the (p, pattern) table.
// One block per plaquette p, 512 threads.
// Phase 1: threads 0..127 (one per m) compute partial products:
//   SB[lo][m] = prod_{s=0..3} eps[bit_s(lo), p, m, s]   (16 entries)
//   SA[hi][m] = prod_{s=4..8} eps[bit_s(hi), p, m, s]   (32 entries)
// stored [half][m] so phase 2 reads float4 along m (conflict-free).
// Phase 2: thread q (one per pattern) computes sum_m SA[hi][m]*SB[lo][m].
// ---------------------------------------------------------------------------
__global__ __launch_bounds__(512, 1)
void build_table_kernel(const float* __restrict__ eps)
{
    const int p   = blockIdx.x;
    const int tid = threadIdx.x;

    __shared__ __align__(16) float sSA[32 * M_DIM];  // 16 KB  [hi][m]
    __shared__ __align__(16) float sSB[16 * M_DIM];  //  8 KB  [lo][m]

    if (tid < M_DIM) {
        const int m = tid;
        // epsilon layout: [o][p][m][s], s contiguous
        const float* e0p = eps + ((size_t)(0 * N_PLAQ + p) * M_DIM + m) * S_SIZE;
        const float* e1p = eps + ((size_t)(1 * N_PLAQ + p) * M_DIM + m) * S_SIZE;
        float a0[S_SIZE], a1[S_SIZE];
        #pragma unroll
        for (int s = 0; s < S_SIZE; s++) { a0[s] = e0p[s]; a1[s] = e1p[s]; }

        // SB: s = 0..3, 16 subsets
        #pragma unroll
        for (int lo = 0; lo < 16; lo++) {
            float v = ((lo & 1) ? a1[0] : a0[0]);
            v *= ((lo & 2) ? a1[1] : a0[1]);
            v *= ((lo & 4) ? a1[2] : a0[2]);
            v *= ((lo & 8) ? a1[3] : a0[3]);
            sSB[lo * M_DIM + m] = v;
        }
        // SA: s = 4..8, 32 subsets
        #pragma unroll
        for (int hi = 0; hi < 32; hi++) {
            float v = ((hi & 1)  ? a1[4] : a0[4]);
            v *= ((hi & 2)  ? a1[5] : a0[5]);
            v *= ((hi & 4)  ? a1[6] : a0[6]);
            v *= ((hi & 8)  ? a1[7] : a0[7]);
            v *= ((hi & 16) ? a1[8] : a0[8]);
            sSA[hi * M_DIM + m] = v;
        }
    }
    __syncthreads();

    // Phase 2: one pattern per thread
    const int q  = tid;           // 0..511
    const int hi = q >> 4;        // bits for s=4..8
    const int lo = q & 15;        // bits for s=0..3
    const float4* A = reinterpret_cast<const float4*>(sSA + hi * M_DIM);
    const float4* B = reinterpret_cast<const float4*>(sSB + lo * M_DIM);

    float acc = 0.0f;
    #pragma unroll 8
    for (int i = 0; i < M_DIM / 4; i++) {
        float4 a = A[i];
        float4 b = B[i];
        acc += a.x * b.x + a.y * b.y + a.z * b.z + a.w * b.w;
    }
    g_table[p * N_PAT + q] = acc;
}

// ---------------------------------------------------------------------------
// Kernel 2: per-batch lookup + reduce.
// 512 threads / block, 8 batches / block (64 threads per batch, one per p).
// ---------------------------------------------------------------------------
#define BPB 8   // batches per block
#define NTHR 512

__global__ __launch_bounds__(NTHR, 4)
void lookup_kernel(const int* __restrict__ inputs,
                   const int* __restrict__ plq,
                   float* __restrict__ out)
{
    const int tid = threadIdx.x;
    const int g   = tid >> 6;          // batch slot in block (0..7)
    const int p   = tid & 63;          // plaquette index
    const int b   = blockIdx.x * BPB + g;

    __shared__ int   s_plq[N_PLAQ * S_SIZE];   // 576 ints
    __shared__ int   s_occ[BPB][L_SITES];      // 8 x 64 ints
    __shared__ float s_red[NTHR / 32];         // 16 warp partials

    // Coalesced: block covers BPB consecutive batch rows linearly.
    s_occ[g][p] = inputs[b * L_SITES + p];
    // FIX: 576 > 512 threads — strided loop so ALL entries get loaded.
    for (int i = tid; i < N_PLAQ * S_SIZE; i += NTHR) s_plq[i] = plq[i];
    __syncthreads();

    // Build 9-bit pattern for plaquette p of batch b
    int pat = 0;
    #pragma unroll
    for (int s = 0; s < S_SIZE; s++) {
        pat |= (s_occ[g][s_plq[p * S_SIZE + s]] & 1) << s;
    }

    float v = __ldg(&g_table[p * N_PAT + pat]);

    // Reduce 64 values (2 warps) per batch slot
    #pragma unroll
    for (int off = 16; off > 0; off >>= 1)
        v += __shfl_xor_sync(0xFFFFFFFFu, v, off);

    const int warp = tid >> 5;
    if ((tid & 31) == 0) s_red[warp] = v;
    __syncthreads();

    if (p == 0) {
        out[b] = s_red[2 * g] + s_red[2 * g + 1];
    }
}

// ---------------------------------------------------------------------------
extern "C" void kernel_launch(void* const* d_in, const int* in_sizes, int n_in,
                              void* d_out, int out_size)
{
    // Identify inputs by element count (all three are distinct):
    //   inputs:     2048*64      = 131072  (int32)
    //   plaquettes: 64*9         = 576     (int32)
    //   epsilon:    2*64*128*9   = 147456  (float32)
    const int*   inputs = nullptr;
    const int*   plq    = nullptr;
    const float* eps    = nullptr;
    for (int i = 0; i < n_in; i++) {
        if      (in_sizes[i] == BATCH * L_SITES)  inputs = (const int*)d_in[i];
        else if (in_sizes[i] == N_PLAQ * S_SIZE)  plq    = (const int*)d_in[i];
        else if (in_sizes[i] == LOCAL_D * N_PLAQ * M_DIM * S_SIZE)
                                                  eps    = (const float*)d_in[i];
    }
    float* out = (float*)d_out;   // (2048,) float32

    build_table_kernel<<<N_PLAQ, 512>>>(eps);
    lookup_kernel<<<BATCH / BPB, NTHR>>>(inputs, plq, out);
}

// round 4
// speedup vs baseline: 1.7112x; 1.7112x over previous
#include <cuda_runtime.h>
#include <stdint.h>

#define GRID_N   8
#define L_SITES  64
#define S_SIZE   9
#define N_PLAQ   64
#define LOCAL_D  2
#define M_DIM    128
#define BATCH    2048
#define N_PAT    512         // 2^9

// Scratch table: T[p][pattern] = sum_m prod_s eps[bit_s, p, m, s]
__device__ float g_table[N_PLAQ * N_PAT];   // 512 KB (L2-resident)

// Padded shared strides: 132 floats = 528 B (16B-aligned).
// B phase-2 bank pattern: lo*132 mod 32 = lo*4 mod 32 -> 2-way max (=256B/warp floor).
#define SA_STR 132
#define SB_STR 132

// ---------------------------------------------------------------------------
// Kernel 1: build (p, pattern) table. One block per plaquette, 512 threads.
// Phase 1 (all 512 threads): thread = (m, part); parts split the 48 subset
// rows:  part0: lo 0..7, part1: lo 8..15 (SB, s=0..3)
//        part2: hi 0..15, part3: hi 16..31 (SA, s=4..8)
// Phase 2: thread q = one 9-bit pattern; dot(SA[hi], SB[lo]) over m, float4.
// ---------------------------------------------------------------------------
__global__ __launch_bounds__(512, 1)
void build_table_kernel(const float* __restrict__ eps)
{
    const int p   = blockIdx.x;
    const int tid = threadIdx.x;

    __shared__ __align__(16) float sSA[32 * SA_STR];  // ~16.5 KB
    __shared__ __align__(16) float sSB[16 * SB_STR];  //  ~8.3 KB

    {
        const int m    = tid & 127;
        const int part = tid >> 7;
        const float* e0p = eps + ((size_t)(0 * N_PLAQ + p) * M_DIM + m) * S_SIZE;
        const float* e1p = eps + ((size_t)(1 * N_PLAQ + p) * M_DIM + m) * S_SIZE;
        float a0[S_SIZE], a1[S_SIZE];
        #pragma unroll
        for (int s = 0; s < S_SIZE; s++) { a0[s] = __ldg(e0p + s); a1[s] = __ldg(e1p + s); }

        if (part < 2) {
            const int base = part * 8;
            #pragma unroll
            for (int k = 0; k < 8; k++) {
                const int lo = base + k;
                float v = ((lo & 1) ? a1[0] : a0[0]);
                v *= ((lo & 2) ? a1[1] : a0[1]);
                v *= ((lo & 4) ? a1[2] : a0[2]);
                v *= ((lo & 8) ? a1[3] : a0[3]);
                sSB[lo * SB_STR + m] = v;
            }
        } else {
            const int base = (part - 2) * 16;
            #pragma unroll
            for (int k = 0; k < 16; k++) {
                const int hi = base + k;
                float v = ((hi & 1)  ? a1[4] : a0[4]);
                v *= ((hi & 2)  ? a1[5] : a0[5]);
                v *= ((hi & 4)  ? a1[6] : a0[6]);
                v *= ((hi & 8)  ? a1[7] : a0[7]);
                v *= ((hi & 16) ? a1[8] : a0[8]);
                sSA[hi * SA_STR + m] = v;
            }
        }
    }
    __syncthreads();

    // Phase 2: one pattern per thread
    const int q  = tid;           // 0..511
    const int hi = q >> 4;
    const int lo = q & 15;
    const float4* A = reinterpret_cast<const float4*>(sSA + hi * SA_STR);
    const float4* B = reinterpret_cast<const float4*>(sSB + lo * SB_STR);

    float acc = 0.0f;
    #pragma unroll 8
    for (int i = 0; i < M_DIM / 4; i++) {
        float4 a = A[i];
        float4 b = B[i];
        acc += a.x * b.x + a.y * b.y + a.z * b.z + a.w * b.w;
    }
    g_table[p * N_PAT + q] = acc;
}

// ---------------------------------------------------------------------------
// Kernel 2: one WARP per batch. No shared memory, no __syncthreads.
//  - pack 64 occupancies into a 64-bit mask via 2x ballot (coalesced loads)
//  - pattern per plaquette computed arithmetically from the 3x3 torus window
//  - lane handles plaquettes (lane, lane+32): 2 L2 lookups, shuffle-reduce
// ---------------------------------------------------------------------------
#define WARPS_PER_BLK 16

__global__ __launch_bounds__(32 * WARPS_PER_BLK, 2)
void lookup_kernel(const int* __restrict__ inputs,
                   float* __restrict__ out)
{
    const int lane = threadIdx.x & 31;
    const int warp = threadIdx.x >> 5;
    const int b    = blockIdx.x * WARPS_PER_BLK + warp;

    // Occupancy bitmask: bit (site) = inputs[b][site] & 1
    const int* row = inputs + (size_t)b * L_SITES;
    const unsigned mlo = __ballot_sync(0xFFFFFFFFu, row[lane]      & 1); // sites 0..31
    const unsigned mhi = __ballot_sync(0xFFFFFFFFu, row[lane + 32] & 1); // sites 32..63

    float acc = 0.0f;
    #pragma unroll
    for (int pp = 0; pp < 2; pp++) {
        const int p = lane + 32 * pp;
        const int i = p >> 3;
        const int j = p & 7;
        int pat = 0;
        #pragma unroll
        for (int di = 0; di < 3; di++) {
            const int r = (i + di) & 7;
            unsigned rowbyte = ((r < 4) ? mlo : mhi) >> ((r & 3) * 8);
            rowbyte &= 0xFFu;
            const unsigned dup = rowbyte | (rowbyte << 8);   // wraparound cols
            pat |= (int)((dup >> j) & 7u) << (3 * di);       // bits dj=0,1,2
        }
        acc += __ldg(&g_table[p * N_PAT + pat]);
    }

    // 32 -> 1 reduce
    #pragma unroll
    for (int off = 16; off > 0; off >>= 1)
        acc += __shfl_xor_sync(0xFFFFFFFFu, acc, off);

    if (lane == 0) out[b] = acc;
}

// ---------------------------------------------------------------------------
extern "C" void kernel_launch(void* const* d_in, const int* in_sizes, int n_in,
                              void* d_out, int out_size)
{
    // Identify inputs by element count (all distinct):
    //   inputs: 131072 int32, plaquettes: 576 int32, epsilon: 147456 f32
    const int*   inputs = nullptr;
    const float* eps    = nullptr;
    for (int i = 0; i < n_in; i++) {
        if      (in_sizes[i] == BATCH * L_SITES) inputs = (const int*)d_in[i];
        else if (in_sizes[i] == LOCAL_D * N_PLAQ * M_DIM * S_SIZE)
                                                 eps    = (const float*)d_in[i];
    }
    float* out = (float*)d_out;

    build_table_kernel<<<N_PLAQ, 512>>>(eps);
    lookup_kernel<<<BATCH / WARPS_PER_BLK, 32 * WARPS_PER_BLK>>>(inputs, out);
}